// round 10
// baseline (speedup 1.0000x reference)
#include <cuda_runtime.h>
#include <cstdint>

#define N_NODES   1000000
#define DIM       128
#define B_GRAPHS  2048
#define CROWS     32                 // rows per chunk
#define ROWB      512                // bytes per row (128 fp32)
#define CBYTES    (CROWS * ROWB)     // 16 KB
#define NBUF      4                  // 0,1 = pipeline ping-pong; 2,3 = tail cache
#define DYN_SMEM  (NBUF * CBYTES)    // 64 KB

// Scratch (no cudaMalloc allowed): transposed W for coalesced GEMM reads
__device__ float g_Wt[DIM * DIM];

__global__ void transpose_W_kernel(const float* __restrict__ W) {
    int i = blockIdx.x * blockDim.x + threadIdx.x;
    if (i < DIM * DIM) {
        int j = i >> 7;
        int k = i & (DIM - 1);
        g_Wt[k * DIM + j] = W[i];
    }
}

// ---- TMA / mbarrier helpers (1D bulk copies) -------------------------------
__device__ __forceinline__ uint32_t s2u(const void* p) {
    return (uint32_t)__cvta_generic_to_shared(p);
}
__device__ __forceinline__ void mbar_init1(uint32_t a) {
    asm volatile("mbarrier.init.shared.b64 [%0], 1;" :: "r"(a) : "memory");
}
__device__ __forceinline__ void tma_fetch(uint32_t mbar, uint32_t dst,
                                          const void* src, uint32_t bytes) {
    asm volatile("mbarrier.arrive.expect_tx.shared.b64 _, [%0], %1;"
                 :: "r"(mbar), "r"(bytes) : "memory");
    asm volatile("cp.async.bulk.shared::cta.global.mbarrier::complete_tx::bytes "
                 "[%0], [%1], %2, [%3];"
                 :: "r"(dst), "l"(src), "r"(bytes), "r"(mbar) : "memory");
}
__device__ __forceinline__ void mbar_wait(uint32_t a, uint32_t parity) {
    asm volatile(
        "{\n\t.reg .pred P;\n"
        "W%=:\n\t"
        "mbarrier.try_wait.parity.acquire.cta.shared::cta.b64 P, [%0], %1, 0x989680;\n\t"
        "@P bra D%=;\n\t"
        "bra W%=;\n"
        "D%=:\n\t}"
        :: "r"(a), "r"(parity) : "memory");
}

// Buffer routing: last 2 chunks of a graph live in dedicated cache slots (2,3)
// and are fetched ONCE (pass 1) then re-consumed from smem in pass 2.
__device__ __forceinline__ int dest_buf(int c, int nc) {
    return (c >= nc - 2) ? (2 + c - (nc - 2)) : (c & 1);
}

// ---------------------------------------------------------------------------
// Fused kernel: one block per graph (sorted seg -> contiguous row range).
// 64KB dynamic smem -> 3 blocks/SM. TMA keeps 96KB/SM in flight (latency
// hiding independent of the low occupancy), smaller residency widens the L2
// reuse window for pass 2, and the 2-chunk smem tail cache is free reuse.
// ---------------------------------------------------------------------------
__global__ void __launch_bounds__(128)
fused_vn_kernel(const float* __restrict__ h,
                const float* __restrict__ vn_h,
                const float* __restrict__ bias,
                const int*   __restrict__ seg,
                float*       __restrict__ vn_out,
                float*       __restrict__ h_out) {
    extern __shared__ __align__(1024) float4 dynsmem[];   // NBUF x 16 KB
    __shared__ float spool[4][DIM];
    __shared__ float sx[DIM];
    __shared__ float svn[DIM];
    __shared__ int   sbounds[2];
    __shared__ __align__(8) unsigned long long smbar[NBUF];

    const int g  = blockIdx.x;
    const int t  = threadIdx.x;
    const int sg = t >> 5;      // warp = row subgroup
    const int ln = t & 31;      // float4 lane within a row

    if (t < 2) {                // bounds via binary search
        int target = g + t, lo = 0, hi = N_NODES;
        while (lo < hi) {
            int mid = (lo + hi) >> 1;
            if (__ldg(&seg[mid]) < target) lo = mid + 1;
            else                           hi = mid;
        }
        sbounds[t] = lo;
    }
    uint32_t mb[NBUF], bufa[NBUF];
    #pragma unroll
    for (int i = 0; i < NBUF; ++i) {
        mb[i]   = s2u(&smbar[i]);
        bufa[i] = s2u(&dynsmem[i * (CBYTES / 16)]);
    }
    if (t == 0) {
        #pragma unroll
        for (int i = 0; i < NBUF; ++i) mbar_init1(mb[i]);
        asm volatile("fence.proxy.async.shared::cta;" ::: "memory");
    }
    __syncthreads();

    const int start = sbounds[0], end = sbounds[1];
    const int rows  = end - start;
    const int nc    = (rows + CROWS - 1) / CROWS;
    const char* gsrc = (const char*)h + (size_t)start * ROWB;
    int kb0 = 0, kb1 = 0;       // pipeline-buffer phase counters

    // --- pass 1 prologue: first two chunks + all remaining cache chunks
    if (t == 0) {
        for (int c = 0; c < nc && c < 2; ++c)
            tma_fetch(mb[dest_buf(c, nc)], bufa[dest_buf(c, nc)],
                      gsrc + (size_t)c * CBYTES,
                      (uint32_t)min(CROWS, rows - c * CROWS) * ROWB);
        for (int c = (nc - 2 > 2 ? nc - 2 : 2); c < nc; ++c)
            tma_fetch(mb[dest_buf(c, nc)], bufa[dest_buf(c, nc)],
                      gsrc + (size_t)c * CBYTES,
                      (uint32_t)min(CROWS, rows - c * CROWS) * ROWB);
    }

    // --- pass 1: segment sum from smem chunks
    float4 a = make_float4(0.f, 0.f, 0.f, 0.f);
    for (int c = 0; c < nc; ++c) {
        int d = dest_buf(c, nc);
        if (d >= 2)      mbar_wait(mb[d], 0);                  // cache: single use
        else if (d == 1) { mbar_wait(mb[1], kb1 & 1); ++kb1; }
        else             { mbar_wait(mb[0], kb0 & 1); ++kb0; }
        int rn = min(CROWS, rows - c * CROWS);
        const float4* sb = &dynsmem[d * (CBYTES / 16)];
        #pragma unroll
        for (int r = sg; r < CROWS; r += 4) {
            if (r < rn) {
                float4 v = sb[r * 32 + ln];
                a.x += v.x; a.y += v.y; a.z += v.z; a.w += v.w;
            }
        }
        __syncthreads();                        // buffer free for refill
        int c2 = c + 2;
        if (t == 0 && c2 < nc - 2)              // cache chunks already fetched
            tma_fetch(mb[c2 & 1], bufa[c2 & 1], gsrc + (size_t)c2 * CBYTES,
                      (uint32_t)CBYTES);
    }

    // --- reduce warp partials -> pool
    ((float4*)&spool[sg][0])[ln] = a;
    __syncthreads();
    float pool = spool[0][t] + spool[1][t] + spool[2][t] + spool[3][t];

    float vh = __ldg(&vn_h[g * DIM + t]);
    sx[t] = vh + pool;
    __syncthreads();

    // --- pass 2 prologue (overlaps GEMM): first two PIPELINE chunks (reverse)
    if (t == 0) {
        if (nc - 3 >= 0)
            tma_fetch(mb[(nc - 3) & 1], bufa[(nc - 3) & 1],
                      gsrc + (size_t)(nc - 3) * CBYTES, (uint32_t)CBYTES);
        if (nc - 4 >= 0)
            tma_fetch(mb[(nc - 4) & 1], bufa[(nc - 4) & 1],
                      gsrc + (size_t)(nc - 4) * CBYTES, (uint32_t)CBYTES);
    }

    // --- VN GEMM: vn = vn_h + relu(sx @ W^T + b)
    float acc0 = 0.f, acc1 = 0.f;
    #pragma unroll 8
    for (int k = 0; k < DIM; k += 2) {
        acc0 = fmaf(sx[k],     __ldg(&g_Wt[k * DIM + t]),       acc0);
        acc1 = fmaf(sx[k + 1], __ldg(&g_Wt[(k + 1) * DIM + t]), acc1);
    }
    float vn = vh + fmaxf(acc0 + acc1 + __ldg(&bias[t]), 0.f);
    vn_out[g * DIM + t] = vn;
    svn[t] = vn;
    __syncthreads();
    float4 vnv = ((const float4*)svn)[ln];

    // --- pass 2: reverse chunk order. Cache chunks come straight from smem;
    //     pipeline chunks via refetch (tail of pass-1 stream -> L2 hits).
    float4* o4 = (float4*)h_out;
    for (int j = 0; j < nc; ++j) {
        int c = nc - 1 - j;
        int d = dest_buf(c, nc);
        if (d < 2) {
            if (d == 1) { mbar_wait(mb[1], kb1 & 1); ++kb1; }
            else        { mbar_wait(mb[0], kb0 & 1); ++kb0; }
        }                                        // cache: data already resident
        int rn = min(CROWS, rows - c * CROWS);
        const float4* sb = &dynsmem[d * (CBYTES / 16)];
        size_t obase = (size_t)(start + c * CROWS) * 32;
        #pragma unroll
        for (int r = sg; r < CROWS; r += 4) {
            if (r < rn) {
                float4 v = sb[r * 32 + ln];
                __stcs(&o4[obase + r * 32 + ln],
                       make_float4(v.x + vnv.x, v.y + vnv.y,
                                   v.z + vnv.z, v.w + vnv.w));
            }
        }
        __syncthreads();
        int c2 = c - 2;                          // refill freed pipeline buffer
        if (t == 0 && c <= nc - 3 && c2 >= 0)
            tma_fetch(mb[c2 & 1], bufa[c2 & 1], gsrc + (size_t)c2 * CBYTES,
                      (uint32_t)CBYTES);
    }
}

// ---------------------------------------------------------------------------
// Launch: out = [vn_out (B*DIM floats) | h_out (N*DIM floats)]
// ---------------------------------------------------------------------------
extern "C" void kernel_launch(void* const* d_in, const int* in_sizes, int n_in,
                              void* d_out, int out_size) {
    const float* h    = (const float*)d_in[0];
    const float* vn_h = (const float*)d_in[1];
    const float* W    = (const float*)d_in[2];
    const float* b    = (const float*)d_in[3];
    const int*   seg  = (const int*)  d_in[4];

    float* out    = (float*)d_out;
    float* vn_out = out;                       // [B, DIM]
    float* h_out  = out + B_GRAPHS * DIM;      // [N, DIM]

    cudaFuncSetAttribute(fused_vn_kernel,
                         cudaFuncAttributeMaxDynamicSharedMemorySize, DYN_SMEM);

    transpose_W_kernel<<<(DIM * DIM + 255) / 256, 256>>>(W);
    fused_vn_kernel<<<B_GRAPHS, DIM, DYN_SMEM>>>(h, vn_h, b, seg, vn_out, h_out);
}

// round 11
// speedup vs baseline: 1.0831x; 1.0831x over previous
#include <cuda_runtime.h>
#include <cstdint>

#define N_NODES   1000000
#define DIM       128
#define B_GRAPHS  2048
#define CROWS     32                 // rows per chunk
#define ROWB      512                // bytes per row (128 fp32)
#define CBYTES    (CROWS * ROWB)     // 16 KB
#define NBUF      4                  // depth-4 ring
#define DYN_SMEM  (NBUF * CBYTES)    // 64 KB -> 3 blocks/SM

// Scratch (no cudaMalloc allowed): transposed W for coalesced GEMM reads
__device__ float g_Wt[DIM * DIM];

__global__ void transpose_W_kernel(const float* __restrict__ W) {
    int i = blockIdx.x * blockDim.x + threadIdx.x;
    if (i < DIM * DIM) {
        int j = i >> 7;
        int k = i & (DIM - 1);
        g_Wt[k * DIM + j] = W[i];
    }
}

// ---- TMA / mbarrier helpers (1D bulk copies) -------------------------------
__device__ __forceinline__ uint32_t s2u(const void* p) {
    return (uint32_t)__cvta_generic_to_shared(p);
}
__device__ __forceinline__ void mbar_init1(uint32_t a) {
    asm volatile("mbarrier.init.shared.b64 [%0], 1;" :: "r"(a) : "memory");
}
__device__ __forceinline__ void tma_fetch(uint32_t mbar, uint32_t dst,
                                          const void* src, uint32_t bytes) {
    asm volatile("mbarrier.arrive.expect_tx.shared.b64 _, [%0], %1;"
                 :: "r"(mbar), "r"(bytes) : "memory");
    asm volatile("cp.async.bulk.shared::cta.global.mbarrier::complete_tx::bytes "
                 "[%0], [%1], %2, [%3];"
                 :: "r"(dst), "l"(src), "r"(bytes), "r"(mbar) : "memory");
}
__device__ __forceinline__ void mbar_wait(uint32_t a, uint32_t parity) {
    asm volatile(
        "{\n\t.reg .pred P;\n"
        "W%=:\n\t"
        "mbarrier.try_wait.parity.acquire.cta.shared::cta.b64 P, [%0], %1, 0x989680;\n\t"
        "@P bra D%=;\n\t"
        "bra W%=;\n"
        "D%=:\n\t}"
        :: "r"(a), "r"(parity) : "memory");
}

// ---------------------------------------------------------------------------
// Fused kernel: one block per graph (sorted seg -> contiguous row range).
// Uniform depth-4 TMA ring over BOTH passes, driven by one fetch counter f:
//   buffer = f & 3, mbarrier parity = (f >> 2) & 1.
// Fetch order: pass-1 chunks 0..nc-1 (f=0..nc-1), then pass-2 chunks in
// REVERSE nc-1..0 (f=nc..2nc-1). 3 blocks/SM x 4 buffers = 12 outstanding
// 16KB fetches/SM (192KB in flight) — latency hiding independent of occ.
// Reverse pass 2 re-reads the tail of the pass-1 stream -> L2 hits; .cs
// stores keep the L2 window clean. GEMM overlaps in-flight pass-2 fetches.
// ---------------------------------------------------------------------------
__global__ void __launch_bounds__(128)
fused_vn_kernel(const float* __restrict__ h,
                const float* __restrict__ vn_h,
                const float* __restrict__ bias,
                const int*   __restrict__ seg,
                float*       __restrict__ vn_out,
                float*       __restrict__ h_out) {
    extern __shared__ __align__(1024) float4 dynsmem[];   // NBUF x 16 KB
    __shared__ float spool[4][DIM];
    __shared__ float sx[DIM];
    __shared__ float svn[DIM];
    __shared__ int   sbounds[2];
    __shared__ __align__(8) unsigned long long smbar[NBUF];

    const int g  = blockIdx.x;
    const int t  = threadIdx.x;
    const int sg = t >> 5;      // warp = row subgroup
    const int ln = t & 31;      // float4 lane within a row

    if (t < 2) {                // bounds via binary search
        int target = g + t, lo = 0, hi = N_NODES;
        while (lo < hi) {
            int mid = (lo + hi) >> 1;
            if (__ldg(&seg[mid]) < target) lo = mid + 1;
            else                           hi = mid;
        }
        sbounds[t] = lo;
    }
    uint32_t mb[NBUF], bufa[NBUF];
    #pragma unroll
    for (int i = 0; i < NBUF; ++i) {
        mb[i]   = s2u(&smbar[i]);
        bufa[i] = s2u(&dynsmem[i * (CBYTES / 16)]);
    }
    if (t == 0) {
        #pragma unroll
        for (int i = 0; i < NBUF; ++i) mbar_init1(mb[i]);
        asm volatile("fence.proxy.async.shared::cta;" ::: "memory");
    }
    __syncthreads();

    const int start   = sbounds[0], end = sbounds[1];
    const int rows    = end - start;
    const int nc      = (rows + CROWS - 1) / CROWS;
    const int total_f = 2 * nc;
    const char* gsrc  = (const char*)h + (size_t)start * ROWB;

    // issue fetch number f (maps to source chunk, forward then reverse)
    auto issue = [&](int f) {
        int cs = (f < nc) ? f : (2 * nc - 1 - f);
        uint32_t bytes = (uint32_t)min(CROWS, rows - cs * CROWS) * ROWB;
        tma_fetch(mb[f & 3], bufa[f & 3], gsrc + (size_t)cs * CBYTES, bytes);
    };

    // --- prologue: fill the ring
    if (t == 0)
        for (int f = 0; f < total_f && f < NBUF; ++f) issue(f);

    // --- pass 1: segment sum from smem chunks (f = c)
    float4 a = make_float4(0.f, 0.f, 0.f, 0.f);
    for (int c = 0; c < nc; ++c) {
        mbar_wait(mb[c & 3], (c >> 2) & 1);
        int rn = min(CROWS, rows - c * CROWS);
        const float4* sb = &dynsmem[(c & 3) * (CBYTES / 16)];
        #pragma unroll
        for (int r = sg; r < CROWS; r += 4) {
            if (r < rn) {
                float4 v = sb[r * 32 + ln];
                a.x += v.x; a.y += v.y; a.z += v.z; a.w += v.w;
            }
        }
        __syncthreads();                        // buffer free for refill
        if (t == 0 && c + NBUF < total_f) issue(c + NBUF);
    }

    // --- reduce warp partials -> pool
    ((float4*)&spool[sg][0])[ln] = a;
    __syncthreads();
    float pool = spool[0][t] + spool[1][t] + spool[2][t] + spool[3][t];

    float vh = __ldg(&vn_h[g * DIM + t]);
    sx[t] = vh + pool;
    __syncthreads();

    // --- VN GEMM (overlaps the in-flight pass-2 fetches issued above)
    float acc0 = 0.f, acc1 = 0.f;
    #pragma unroll 8
    for (int k = 0; k < DIM; k += 2) {
        acc0 = fmaf(sx[k],     __ldg(&g_Wt[k * DIM + t]),       acc0);
        acc1 = fmaf(sx[k + 1], __ldg(&g_Wt[(k + 1) * DIM + t]), acc1);
    }
    float vn = vh + fmaxf(acc0 + acc1 + __ldg(&bias[t]), 0.f);
    vn_out[g * DIM + t] = vn;
    svn[t] = vn;
    __syncthreads();
    float4 vnv = ((const float4*)svn)[ln];

    // --- pass 2: reverse chunk order (f = nc + j, source chunk nc-1-j)
    float4* o4 = (float4*)h_out;
    for (int j = 0; j < nc; ++j) {
        int f  = nc + j;
        int cs = nc - 1 - j;
        mbar_wait(mb[f & 3], (f >> 2) & 1);
        int rn = min(CROWS, rows - cs * CROWS);
        const float4* sb = &dynsmem[(f & 3) * (CBYTES / 16)];
        size_t obase = (size_t)(start + cs * CROWS) * 32;
        #pragma unroll
        for (int r = sg; r < CROWS; r += 4) {
            if (r < rn) {
                float4 v = sb[r * 32 + ln];
                __stcs(&o4[obase + r * 32 + ln],
                       make_float4(v.x + vnv.x, v.y + vnv.y,
                                   v.z + vnv.z, v.w + vnv.w));
            }
        }
        __syncthreads();
        if (t == 0 && f + NBUF < total_f) issue(f + NBUF);
    }
}

// ---------------------------------------------------------------------------
// Launch: out = [vn_out (B*DIM floats) | h_out (N*DIM floats)]
// ---------------------------------------------------------------------------
extern "C" void kernel_launch(void* const* d_in, const int* in_sizes, int n_in,
                              void* d_out, int out_size) {
    const float* h    = (const float*)d_in[0];
    const float* vn_h = (const float*)d_in[1];
    const float* W    = (const float*)d_in[2];
    const float* b    = (const float*)d_in[3];
    const int*   seg  = (const int*)  d_in[4];

    float* out    = (float*)d_out;
    float* vn_out = out;                       // [B, DIM]
    float* h_out  = out + B_GRAPHS * DIM;      // [N, DIM]

    cudaFuncSetAttribute(fused_vn_kernel,
                         cudaFuncAttributeMaxDynamicSharedMemorySize, DYN_SMEM);

    transpose_W_kernel<<<(DIM * DIM + 255) / 256, 256>>>(W);
    fused_vn_kernel<<<B_GRAPHS, DIM, DYN_SMEM>>>(h, vn_h, b, seg, vn_out, h_out);
}